// round 5
// baseline (speedup 1.0000x reference)
#include <cuda_runtime.h>
#include <cuda_bf16.h>
#include <math.h>

// EMA with SD — single fused kernel with decoupled look-back (round 5).
// x (T=8192, D=128); h_a0, h_sd0, alpha (N=32, D=128).
// out: (T, 2N, D) fp32, then hN_a (N,D), hN_sd (N,D).
//
// C=64 chunks of L=128. Per chunk (per lane):
//   chunk-end h_a = W*h_a0 + P                      (W = beta^L, closed form)
//   chunk-end h_v = W*h_v0 + A + B*h_a0 + C*h_a0^2
//     A = sum_i beta^{L-1-i}*beta*alpha*u_i^2  (loop accumulator)
//     B = -2*beta*alpha*beta^{L-1} * S,  S = sum_i u_i
//     C = W*(1-W)
// Each block (c,n): summarize own chunk -> publish -> fold predecessors'
// summaries (spin on count-flags) -> exact replay with streaming stores.
// All 2048 blocks (32 thr) are co-resident in one wave => no deadlock.

#define TT 8192
#define DD 128
#define NN 32
#define CC 64
#define LL 128
#define LANES (NN * DD)

__device__ float4 g_P[CC * NN * 32];
__device__ float4 g_A[CC * NN * 32];
__device__ float4 g_S[CC * NN * 32];
__device__ int    g_flag[CC * NN];

__device__ __forceinline__ float sqrt_fast(float v) {
    float r;
    asm("sqrt.approx.f32 %0, %1;" : "=f"(r) : "f"(v));
    return r;
}

__device__ __forceinline__ int ld_vol(const int* p) {
    int v;
    asm volatile("ld.volatile.global.s32 %0, [%1];" : "=r"(v) : "l"(p));
    return v;
}

__global__ __launch_bounds__(32) void ema_fused(
    const float* __restrict__ x,
    const float* __restrict__ h_a0,
    const float* __restrict__ h_sd0,
    const float* __restrict__ alpha,
    float* __restrict__ out,
    int write_tail)
{
    const int n = blockIdx.x;          // 0..31
    const int c = blockIdx.y;          // 0..63  (slow dim -> low c launches first)
    const int t = threadIdx.x;         // 0..31
    const int d = 4 * t;
    const int idx = n * DD + d;

    const float4 al = *reinterpret_cast<const float4*>(alpha + idx);
    const float a0 = al.x, a1 = al.y, a2 = al.z, a3 = al.w;
    const float b0 = 1.0f - a0, b1 = 1.0f - a1, b2 = 1.0f - a2, b3 = 1.0f - a3;
    const float ba0 = b0 * a0, ba1 = b1 * a1, ba2 = b2 * a2, ba3 = b3 * a3;

    const float4* xp = reinterpret_cast<const float4*>(x + (size_t)c * LL * DD + d);

    // ---------------- Phase A: chunk summary ----------------
    float g0 = 0.f, g1 = 0.f, g2 = 0.f, g3 = 0.f;
    float A0 = 0.f, A1 = 0.f, A2 = 0.f, A3 = 0.f;
    float S0 = 0.f, S1 = 0.f, S2 = 0.f, S3 = 0.f;

#pragma unroll 4
    for (int i = 0; i < LL; ++i) {
        const float4 xv = xp[(size_t)i * (DD / 4)];
        const float u0 = xv.x - g0, u1 = xv.y - g1, u2 = xv.z - g2, u3 = xv.w - g3;
        g0 = fmaf(b0, g0, a0 * xv.x);
        g1 = fmaf(b1, g1, a1 * xv.y);
        g2 = fmaf(b2, g2, a2 * xv.z);
        g3 = fmaf(b3, g3, a3 * xv.w);
        A0 = fmaf(b0, A0, ba0 * (u0 * u0));
        A1 = fmaf(b1, A1, ba1 * (u1 * u1));
        A2 = fmaf(b2, A2, ba2 * (u2 * u2));
        A3 = fmaf(b3, A3, ba3 * (u3 * u3));
        S0 += u0; S1 += u1; S2 += u2; S3 += u3;
    }

    const int sbase = (c * NN + n) * 32 + t;
    g_P[sbase] = make_float4(g0, g1, g2, g3);
    g_A[sbase] = make_float4(A0, A1, A2, A3);
    g_S[sbase] = make_float4(S0, S1, S2, S3);
    __threadfence();
    atomicAdd(&g_flag[c * NN + n], 1);   // each thread arrives after its own fence

    // ---------------- Phase B: fold predecessor summaries ----------------
    // per-lane constants: W = b^128, b^127, coefB, Cq
    float W0, W1, W2, W3, cB0, cB1, cB2, cB3, Cq0, Cq1, Cq2, Cq3;
    {
        float p2, p4, p8, p16, p32, p64, b127;
        p2 = b0*b0; p4 = p2*p2; p8 = p4*p4; p16 = p8*p8; p32 = p16*p16; p64 = p32*p32;
        b127 = b0*p2*p4*p8*p16*p32*p64; W0 = p64*p64; Cq0 = W0*(1.f-W0); cB0 = -2.f*ba0*b127;
        p2 = b1*b1; p4 = p2*p2; p8 = p4*p4; p16 = p8*p8; p32 = p16*p16; p64 = p32*p32;
        b127 = b1*p2*p4*p8*p16*p32*p64; W1 = p64*p64; Cq1 = W1*(1.f-W1); cB1 = -2.f*ba1*b127;
        p2 = b2*b2; p4 = p2*p2; p8 = p4*p4; p16 = p8*p8; p32 = p16*p16; p64 = p32*p32;
        b127 = b2*p2*p4*p8*p16*p32*p64; W2 = p64*p64; Cq2 = W2*(1.f-W2); cB2 = -2.f*ba2*b127;
        p2 = b3*b3; p4 = p2*p2; p8 = p4*p4; p16 = p8*p8; p32 = p16*p16; p64 = p32*p32;
        b127 = b3*p2*p4*p8*p16*p32*p64; W3 = p64*p64; Cq3 = W3*(1.f-W3); cB3 = -2.f*ba3*b127;
    }

    const float4 hav = *reinterpret_cast<const float4*>(h_a0 + idx);
    const float4 sdv = *reinterpret_cast<const float4*>(h_sd0 + idx);
    float ha0_ = hav.x, ha1_ = hav.y, ha2_ = hav.z, ha3_ = hav.w;
    float hv0_ = sdv.x * sdv.x, hv1_ = sdv.y * sdv.y, hv2_ = sdv.z * sdv.z, hv3_ = sdv.w * sdv.w;

    for (int cc = 0; cc < c; ++cc) {
        const int fidx = cc * NN + n;
        while (ld_vol(&g_flag[fidx]) < 32) { }
        __threadfence();                      // acquire
        const int sb = fidx * 32 + t;
        const float4 P = g_P[sb];
        const float4 Aa = g_A[sb];
        const float4 Ss = g_S[sb];
        float hvn;
        hvn = fmaf(W0, hv0_, fmaf(Cq0, ha0_*ha0_, fmaf(cB0*Ss.x, ha0_, Aa.x)));
        hv0_ = fmaxf(hvn, 0.f);  ha0_ = fmaf(W0, ha0_, P.x);
        hvn = fmaf(W1, hv1_, fmaf(Cq1, ha1_*ha1_, fmaf(cB1*Ss.y, ha1_, Aa.y)));
        hv1_ = fmaxf(hvn, 0.f);  ha1_ = fmaf(W1, ha1_, P.y);
        hvn = fmaf(W2, hv2_, fmaf(Cq2, ha2_*ha2_, fmaf(cB2*Ss.z, ha2_, Aa.z)));
        hv2_ = fmaxf(hvn, 0.f);  ha2_ = fmaf(W2, ha2_, P.z);
        hvn = fmaf(W3, hv3_, fmaf(Cq3, ha3_*ha3_, fmaf(cB3*Ss.w, ha3_, Aa.w)));
        hv3_ = fmaxf(hvn, 0.f);  ha3_ = fmaf(W3, ha3_, P.w);
    }

    // ---------------- Phase C: exact replay, streaming stores ----------------
    float* obase = out + (size_t)c * LL * (2 * NN * DD) + n * DD + d;

#pragma unroll 4
    for (int i = 0; i < LL; ++i) {
        const float4 xv = xp[(size_t)i * (DD / 4)];
        const float u0 = xv.x - ha0_, u1 = xv.y - ha1_, u2 = xv.z - ha2_, u3 = xv.w - ha3_;
        ha0_ = fmaf(b0, ha0_, a0 * xv.x);
        ha1_ = fmaf(b1, ha1_, a1 * xv.y);
        ha2_ = fmaf(b2, ha2_, a2 * xv.z);
        ha3_ = fmaf(b3, ha3_, a3 * xv.w);
        hv0_ = fmaf(b0, hv0_, ba0 * (u0 * u0));
        hv1_ = fmaf(b1, hv1_, ba1 * (u1 * u1));
        hv2_ = fmaf(b2, hv2_, ba2 * (u2 * u2));
        hv3_ = fmaf(b3, hv3_, ba3 * (u3 * u3));
        float* op = obase + (size_t)i * (2 * NN * DD);
        __stcs(reinterpret_cast<float4*>(op),
               make_float4(ha0_, ha1_, ha2_, ha3_));
        __stcs(reinterpret_cast<float4*>(op + NN * DD),
               make_float4(sqrt_fast(hv0_), sqrt_fast(hv1_), sqrt_fast(hv2_), sqrt_fast(hv3_)));
    }

    // ---------------- tail: final states from the last chunk ----------------
    if (write_tail && c == CC - 1) {
        const size_t base = (size_t)TT * 2 * NN * DD;
        *reinterpret_cast<float4*>(out + base + idx) =
            make_float4(ha0_, ha1_, ha2_, ha3_);
        *reinterpret_cast<float4*>(out + base + LANES + idx) =
            make_float4(sqrt_fast(hv0_), sqrt_fast(hv1_), sqrt_fast(hv2_), sqrt_fast(hv3_));
    }
}

extern "C" void kernel_launch(void* const* d_in, const int* in_sizes, int n_in,
                              void* d_out, int out_size)
{
    const float* x     = (const float*)d_in[0];
    const float* h_a0  = (const float*)d_in[1];
    const float* h_sd0 = (const float*)d_in[2];
    const float* alpha = (const float*)d_in[3];
    float* out = (float*)d_out;

    const int main_elems = TT * 2 * NN * DD;
    const int write_tail = (out_size > main_elems) ? 1 : 0;

    void* flag_ptr = nullptr;
    cudaGetSymbolAddress(&flag_ptr, g_flag);
    cudaMemsetAsync(flag_ptr, 0, CC * NN * sizeof(int));

    dim3 grid(NN, CC);
    ema_fused<<<grid, 32>>>(x, h_a0, h_sd0, alpha, out, write_tail);
}

// round 6
// speedup vs baseline: 1.0465x; 1.0465x over previous
#include <cuda_runtime.h>
#include <cuda_bf16.h>
#include <math.h>

// EMA with SD, chunked parallel scan (round 6).
// x (T=8192, D=128); h_a0, h_sd0, alpha (N=32, D=128).
// out: (T, 2N, D) fp32, then hN_a (N,D), hN_sd (N,D).
//
// C=128 chunks of L=64 steps (doubled occupancy vs round 4):
//   beta = 1 - alpha, W = beta^L (closed form by squaring)
//   chunk-end h_a = W*h_a0 + P,                P = g[L-1]
//   chunk-end h_v = W*h_v0 + A + B*h_a0 + C*h_a0^2
//     A = sum_i beta^{L-1-i}*beta*alpha*u_i^2   (loop accumulator)
//     B = -2*beta*alpha*beta^{L-1} * S,  S = sum_i u_i   (weights cancel)
//     C = W*(1-W)
// pass1: per-(chunk,lane) summaries (P, A, S).
// combine: sequential fold of 128 summaries per lane -> chunk entry states.
// pass2: exact per-step replay, streaming (evict-first) float2 stores.

#define TT 8192
#define DD 128
#define NN 32
#define CC 128
#define LL 64           // TT / CC
#define LANES (NN * DD) // 4096

__device__ float g_P  [CC * LANES];
__device__ float g_A  [CC * LANES];
__device__ float g_S  [CC * LANES];
__device__ float g_ha0[CC * LANES];
__device__ float g_hv0[CC * LANES];

__device__ __forceinline__ float sqrt_fast(float v) {
    float r;
    asm("sqrt.approx.f32 %0, %1;" : "=f"(r) : "f"(v));
    return r;
}

// ---------------------------------------------------------------- pass 1
__global__ __launch_bounds__(64) void ema_pass1(
    const float* __restrict__ x,
    const float* __restrict__ alpha)
{
    const int c  = blockIdx.x;           // 0..CC-1
    const int n  = blockIdx.y;           // 0..NN-1
    const int d2 = threadIdx.x;          // 0..63 -> d = 2*d2, 2*d2+1
    const int idx = n * DD + 2 * d2;

    const float2 al = *reinterpret_cast<const float2*>(alpha + idx);
    const float a0 = al.x, a1 = al.y;
    const float b0 = 1.0f - a0, b1 = 1.0f - a1;
    const float ba0 = b0 * a0, ba1 = b1 * a1;

    const float2* xp = reinterpret_cast<const float2*>(x + (size_t)c * LL * DD + 2 * d2);

    float gA = 0.0f, gB = 0.0f;
    float A0 = 0.0f, A1 = 0.0f;
    float S0 = 0.0f, S1 = 0.0f;

#pragma unroll 8
    for (int i = 0; i < LL; ++i) {
        const float2 xv = xp[(size_t)i * (DD / 2)];
        const float u0 = xv.x - gA;
        const float u1 = xv.y - gB;
        gA = fmaf(b0, gA, a0 * xv.x);
        gB = fmaf(b1, gB, a1 * xv.y);
        A0 = fmaf(b0, A0, ba0 * (u0 * u0));
        A1 = fmaf(b1, A1, ba1 * (u1 * u1));
        S0 += u0;
        S1 += u1;
    }

    const int s = c * LANES + idx;
    *reinterpret_cast<float2*>(g_P + s) = make_float2(gA, gB);
    *reinterpret_cast<float2*>(g_A + s) = make_float2(A0, A1);
    *reinterpret_cast<float2*>(g_S + s) = make_float2(S0, S1);
}

// ---------------------------------------------------------------- combine
__global__ __launch_bounds__(DD) void ema_combine(
    const float* __restrict__ h_a0,
    const float* __restrict__ h_sd0,
    const float* __restrict__ alpha,
    float* __restrict__ out,
    int write_tail)
{
    const int n = blockIdx.x;
    const int d = threadIdx.x;
    const int idx = n * DD + d;

    const float a = alpha[idx];
    const float b = 1.0f - a;
    // b^(L-1)=b^63 and W=b^64 by repeated squaring
    const float s2  = b * b;
    const float s4  = s2 * s2;
    const float s8  = s4 * s4;
    const float s16 = s8 * s8;
    const float s32 = s16 * s16;
    const float b63 = b * s2 * s4 * s8 * s16 * s32;  // b^63
    const float W   = s32 * s32;                     // b^64
    const float Cq  = W * (1.0f - W);
    const float coefB = -2.0f * b * a * b63;

    float ha = h_a0[idx];
    const float sd = h_sd0[idx];
    float hv = sd * sd;

#pragma unroll 8
    for (int c = 0; c < CC; ++c) {
        const int s = c * LANES + idx;
        g_ha0[s] = ha;
        g_hv0[s] = hv;
        const float P = g_P[s];
        const float A = g_A[s];
        const float B = coefB * g_S[s];
        const float hv_new = fmaf(W, hv, fmaf(Cq, ha * ha, fmaf(B, ha, A)));
        hv = fmaxf(hv_new, 0.0f);
        ha = fmaf(W, ha, P);
    }

    if (write_tail) {
        const size_t base = (size_t)TT * 2 * NN * DD;
        out[base + idx]         = ha;          // hN_a
        out[base + LANES + idx] = sqrtf(hv);   // hN_sd
    }
}

// ---------------------------------------------------------------- pass 2
__global__ __launch_bounds__(64) void ema_pass2(
    const float* __restrict__ x,
    const float* __restrict__ alpha,
    float* __restrict__ out)
{
    const int c  = blockIdx.x;
    const int n  = blockIdx.y;
    const int d2 = threadIdx.x;          // 0..63
    const int idx = n * DD + 2 * d2;

    const float2 al = *reinterpret_cast<const float2*>(alpha + idx);
    const float a0 = al.x, a1 = al.y;
    const float b0 = 1.0f - a0, b1 = 1.0f - a1;
    const float ba0 = b0 * a0, ba1 = b1 * a1;

    const int s = c * LANES + idx;
    float2 hav = *reinterpret_cast<const float2*>(g_ha0 + s);
    float2 hvv = *reinterpret_cast<const float2*>(g_hv0 + s);
    float ha0 = hav.x, ha1 = hav.y;
    float hv0 = hvv.x, hv1 = hvv.y;

    const float2* xp = reinterpret_cast<const float2*>(x + (size_t)c * LL * DD + 2 * d2);
    // out row for time t is 2*N*D = 8192 floats = 4096 float2
    float2* obase = reinterpret_cast<float2*>(out + (size_t)c * LL * 2 * NN * DD + n * DD + 2 * d2);

#pragma unroll 8
    for (int i = 0; i < LL; ++i) {
        const float2 xv = xp[(size_t)i * (DD / 2)];
        const float u0 = xv.x - ha0;
        const float u1 = xv.y - ha1;
        ha0 = fmaf(b0, ha0, a0 * xv.x);
        ha1 = fmaf(b1, ha1, a1 * xv.y);
        hv0 = fmaf(b0, hv0, ba0 * (u0 * u0));
        hv1 = fmaf(b1, hv1, ba1 * (u1 * u1));
        float2* op = obase + (size_t)i * (NN * DD);      // i * 4096 float2
        __stcs(op, make_float2(ha0, ha1));
        __stcs(op + (NN * DD / 2), make_float2(sqrt_fast(hv0), sqrt_fast(hv1)));
    }
}

extern "C" void kernel_launch(void* const* d_in, const int* in_sizes, int n_in,
                              void* d_out, int out_size)
{
    const float* x     = (const float*)d_in[0];
    const float* h_a0  = (const float*)d_in[1];
    const float* h_sd0 = (const float*)d_in[2];
    const float* alpha = (const float*)d_in[3];
    float* out = (float*)d_out;

    const int main_elems = TT * 2 * NN * DD;
    const int write_tail = (out_size > main_elems) ? 1 : 0;

    dim3 grid1(CC, NN);
    ema_pass1<<<grid1, 64>>>(x, alpha);
    ema_combine<<<NN, DD>>>(h_a0, h_sd0, alpha, out, write_tail);
    dim3 grid2(CC, NN);
    ema_pass2<<<grid2, 64>>>(x, alpha, out);
}

// round 7
// speedup vs baseline: 1.1292x; 1.0790x over previous
#include <cuda_runtime.h>
#include <cuda_bf16.h>
#include <math.h>

// EMA with SD, chunked parallel scan (round 7).
// x (T=8192, D=128); h_a0, h_sd0, alpha (N=32, D=128).
// out: (T, 2N, D) fp32, then hN_a (N,D), hN_sd (N,D).
//
// Summaries at CS=128 chunks of LS=64 (best measured pass1 config).
// Replay at CR=64 chunks of LR=128 with float4 STG.128 stores
// (store-issue-cost model: STG.128 = 12cyc vs 2x STG.64 = 15.5cyc).
//
//   beta = 1 - alpha, W = beta^LS (closed form by squaring)
//   chunk-end h_a = W*h_a0 + P,                P = g[LS-1]
//   chunk-end h_v = W*h_v0 + A + B*h_a0 + C*h_a0^2
//     A = sum_i beta^{LS-1-i}*beta*alpha*u_i^2
//     B = -2*beta*alpha*beta^{LS-1} * S,  S = sum_i u_i
//     C = W*(1-W)

#define TT 8192
#define DD 128
#define NN 32
#define CS 128
#define LS 64           // TT / CS  (summary chunks)
#define CR 64
#define LR 128          // TT / CR  (replay chunks)
#define LANES (NN * DD) // 4096

__device__ float g_P  [CS * LANES];
__device__ float g_A  [CS * LANES];
__device__ float g_S  [CS * LANES];
__device__ float g_ha0[CR * LANES];
__device__ float g_hv0[CR * LANES];

__device__ __forceinline__ float sqrt_fast(float v) {
    float r;
    asm("sqrt.approx.f32 %0, %1;" : "=f"(r) : "f"(v));
    return r;
}

// ---------------------------------------------------------------- pass 1
// (identical to round-6 measured-best: 14.3us)
__global__ __launch_bounds__(64) void ema_pass1(
    const float* __restrict__ x,
    const float* __restrict__ alpha)
{
    const int c  = blockIdx.x;           // 0..CS-1
    const int n  = blockIdx.y;           // 0..NN-1
    const int d2 = threadIdx.x;          // 0..63 -> d = 2*d2, 2*d2+1
    const int idx = n * DD + 2 * d2;

    const float2 al = *reinterpret_cast<const float2*>(alpha + idx);
    const float a0 = al.x, a1 = al.y;
    const float b0 = 1.0f - a0, b1 = 1.0f - a1;
    const float ba0 = b0 * a0, ba1 = b1 * a1;

    const float2* xp = reinterpret_cast<const float2*>(x + (size_t)c * LS * DD + 2 * d2);

    float gA = 0.0f, gB = 0.0f;
    float A0 = 0.0f, A1 = 0.0f;
    float S0 = 0.0f, S1 = 0.0f;

#pragma unroll 8
    for (int i = 0; i < LS; ++i) {
        const float2 xv = xp[(size_t)i * (DD / 2)];
        const float u0 = xv.x - gA;
        const float u1 = xv.y - gB;
        gA = fmaf(b0, gA, a0 * xv.x);
        gB = fmaf(b1, gB, a1 * xv.y);
        A0 = fmaf(b0, A0, ba0 * (u0 * u0));
        A1 = fmaf(b1, A1, ba1 * (u1 * u1));
        S0 += u0;
        S1 += u1;
    }

    const int s = c * LANES + idx;
    *reinterpret_cast<float2*>(g_P + s) = make_float2(gA, gB);
    *reinterpret_cast<float2*>(g_A + s) = make_float2(A0, A1);
    *reinterpret_cast<float2*>(g_S + s) = make_float2(S0, S1);
}

// ---------------------------------------------------------------- combine
// Folds all CS=128 summaries; writes entry states only at even summary
// chunks (the CR=64 replay-chunk starts).
__global__ __launch_bounds__(DD) void ema_combine(
    const float* __restrict__ h_a0,
    const float* __restrict__ h_sd0,
    const float* __restrict__ alpha,
    float* __restrict__ out,
    int write_tail)
{
    const int n = blockIdx.x;
    const int d = threadIdx.x;
    const int idx = n * DD + d;

    const float a = alpha[idx];
    const float b = 1.0f - a;
    // b^63 and W = b^64 by repeated squaring
    const float s2  = b * b;
    const float s4  = s2 * s2;
    const float s8  = s4 * s4;
    const float s16 = s8 * s8;
    const float s32 = s16 * s16;
    const float b63 = b * s2 * s4 * s8 * s16 * s32;
    const float W   = s32 * s32;
    const float Cq  = W * (1.0f - W);
    const float coefB = -2.0f * b * a * b63;

    float ha = h_a0[idx];
    const float sd = h_sd0[idx];
    float hv = sd * sd;

#pragma unroll 8
    for (int c = 0; c < CS; ++c) {
        if ((c & 1) == 0) {
            const int e = (c >> 1) * LANES + idx;
            g_ha0[e] = ha;
            g_hv0[e] = hv;
        }
        const int s = c * LANES + idx;
        const float P = g_P[s];
        const float A = g_A[s];
        const float B = coefB * g_S[s];
        const float hv_new = fmaf(W, hv, fmaf(Cq, ha * ha, fmaf(B, ha, A)));
        hv = fmaxf(hv_new, 0.0f);
        ha = fmaf(W, ha, P);
    }

    if (write_tail) {
        const size_t base = (size_t)TT * 2 * NN * DD;
        out[base + idx]         = ha;          // hN_a
        out[base + LANES + idx] = sqrtf(hv);   // hN_sd
    }
}

// ---------------------------------------------------------------- pass 2
// Replay with float4 lanes + STG.128 streaming stores.
// Block: 64 threads = 2 warps, each warp = one n (32 threads x 4 d).
__global__ __launch_bounds__(64) void ema_pass2(
    const float* __restrict__ x,
    const float* __restrict__ alpha,
    float* __restrict__ out)
{
    const int c = blockIdx.x;                   // 0..CR-1
    const int n = blockIdx.y * 2 + (threadIdx.x >> 5);  // 0..NN-1
    const int l = threadIdx.x & 31;
    const int d = 4 * l;                        // 0..124
    const int idx = n * DD + d;

    const float4 al = *reinterpret_cast<const float4*>(alpha + idx);
    const float a0 = al.x, a1 = al.y, a2 = al.z, a3 = al.w;
    const float b0 = 1.0f - a0, b1 = 1.0f - a1, b2 = 1.0f - a2, b3 = 1.0f - a3;
    const float ba0 = b0 * a0, ba1 = b1 * a1, ba2 = b2 * a2, ba3 = b3 * a3;

    const int s = c * LANES + idx;
    const float4 hav = *reinterpret_cast<const float4*>(g_ha0 + s);
    const float4 hvv = *reinterpret_cast<const float4*>(g_hv0 + s);
    float ha0 = hav.x, ha1 = hav.y, ha2 = hav.z, ha3 = hav.w;
    float hv0 = hvv.x, hv1 = hvv.y, hv2 = hvv.z, hv3 = hvv.w;

    const float4* xp = reinterpret_cast<const float4*>(x + (size_t)c * LR * DD + d);
    float* obase = out + (size_t)c * LR * (2 * NN * DD) + idx;

#pragma unroll 8
    for (int i = 0; i < LR; ++i) {
        const float4 xv = xp[(size_t)i * (DD / 4)];
        const float u0 = xv.x - ha0, u1 = xv.y - ha1;
        const float u2 = xv.z - ha2, u3 = xv.w - ha3;
        ha0 = fmaf(b0, ha0, a0 * xv.x);
        ha1 = fmaf(b1, ha1, a1 * xv.y);
        ha2 = fmaf(b2, ha2, a2 * xv.z);
        ha3 = fmaf(b3, ha3, a3 * xv.w);
        hv0 = fmaf(b0, hv0, ba0 * (u0 * u0));
        hv1 = fmaf(b1, hv1, ba1 * (u1 * u1));
        hv2 = fmaf(b2, hv2, ba2 * (u2 * u2));
        hv3 = fmaf(b3, hv3, ba3 * (u3 * u3));
        float* op = obase + (size_t)i * (2 * NN * DD);
        __stcs(reinterpret_cast<float4*>(op),
               make_float4(ha0, ha1, ha2, ha3));
        __stcs(reinterpret_cast<float4*>(op + NN * DD),
               make_float4(sqrt_fast(hv0), sqrt_fast(hv1),
                           sqrt_fast(hv2), sqrt_fast(hv3)));
    }
}

extern "C" void kernel_launch(void* const* d_in, const int* in_sizes, int n_in,
                              void* d_out, int out_size)
{
    const float* x     = (const float*)d_in[0];
    const float* h_a0  = (const float*)d_in[1];
    const float* h_sd0 = (const float*)d_in[2];
    const float* alpha = (const float*)d_in[3];
    float* out = (float*)d_out;

    const int main_elems = TT * 2 * NN * DD;
    const int write_tail = (out_size > main_elems) ? 1 : 0;

    dim3 grid1(CS, NN);
    ema_pass1<<<grid1, 64>>>(x, alpha);
    ema_combine<<<NN, DD>>>(h_a0, h_sd0, alpha, out, write_tail);
    dim3 grid2(CR, NN / 2);
    ema_pass2<<<grid2, 64>>>(x, alpha, out);
}